// round 3
// baseline (speedup 1.0000x reference)
#include <cuda_runtime.h>
#include <cstddef>

#define N_ITEMS   100000
#define N_USERS   16384
#define HIST      50
#define TEXT_DIM  256
#define GCN_DIM   128
#define HIDDEN_DIM 512
#define TOWER_DIM 128

#define CDIV(a,b) (((a)+(b)-1)/(b))

// ---------------- scratch (device globals; no allocation allowed) ----------
__device__ float g_H[(size_t)N_ITEMS * HIDDEN_DIM];        // item hidden (205 MB)
__device__ float g_item_emb[(size_t)N_ITEMS * TOWER_DIM];  // item tower out (51 MB)
__device__ float g_user_feat[(size_t)N_USERS * (GCN_DIM + TOWER_DIM)]; // fused user input
__device__ float g_Hu[(size_t)N_USERS * HIDDEN_DIM];       // user hidden

// ---------------- generic tiled SGEMM: C = op(A @ B + bias) ----------------
// A is logically [M, K]; column c < split comes from A0 (lda=split), else from
// A1 (lda=K-split).  B is [K, N] row-major.  BM=BN=128, BK=8, 256 threads,
// 8x8 register tile per thread.  RELU / per-row L2NORM epilogues.
// L2NORM requires N == BN == 128 (single block covers a full row).
template<bool RELU, bool L2NORM>
__global__ __launch_bounds__(256)
void sgemm(const float* __restrict__ A0, const float* __restrict__ A1, int split,
           int M, int N, int K,
           const float* __restrict__ B, const float* __restrict__ bias,
           float* __restrict__ C)
{
    const int BM = 128, BN = 128, BK = 8;
    __shared__ float As[BK][BM];
    __shared__ float Bs[BK][BN];
    __shared__ float red[BM][17];   // L2 partial sums (padded)
    __shared__ float scl[BM];

    const int tid = threadIdx.x;
    const int ty = tid >> 4;        // 0..15
    const int tx = tid & 15;        // 0..15
    const int bm = blockIdx.y, bn = blockIdx.x;

    float acc[8][8];
    #pragma unroll
    for (int i = 0; i < 8; i++)
        #pragma unroll
        for (int j = 0; j < 8; j++) acc[i][j] = 0.f;

    const int ar  = tid >> 1;            // A-tile row 0..127
    const int acb = (tid & 1) * 4;       // A-tile k-offset 0 or 4
    const int grow = bm * BM + ar;       // global A row
    const int brow = tid >> 5;           // B-tile k row 0..7
    const int bcol = (tid & 31) * 4;     // B-tile col
    const int lda1 = K - split;

    for (int k0 = 0; k0 < K; k0 += BK) {
        float4 av = make_float4(0.f, 0.f, 0.f, 0.f);
        const int ac = k0 + acb;
        if (grow < M) {
            const float* src = (ac < split)
                ? (A0 + (size_t)grow * split + ac)
                : (A1 + (size_t)grow * lda1 + (ac - split));
            av = *reinterpret_cast<const float4*>(src);
        }
        const float4 bv = *reinterpret_cast<const float4*>(
            B + (size_t)(k0 + brow) * N + (size_t)bn * BN + bcol);

        __syncthreads();
        As[acb + 0][ar] = av.x;
        As[acb + 1][ar] = av.y;
        As[acb + 2][ar] = av.z;
        As[acb + 3][ar] = av.w;
        *reinterpret_cast<float4*>(&Bs[brow][bcol]) = bv;
        __syncthreads();

        #pragma unroll
        for (int kk = 0; kk < BK; kk++) {
            float a[8], b[8];
            *reinterpret_cast<float4*>(&a[0]) = *reinterpret_cast<float4*>(&As[kk][ty * 8]);
            *reinterpret_cast<float4*>(&a[4]) = *reinterpret_cast<float4*>(&As[kk][ty * 8 + 4]);
            *reinterpret_cast<float4*>(&b[0]) = *reinterpret_cast<float4*>(&Bs[kk][tx * 8]);
            *reinterpret_cast<float4*>(&b[4]) = *reinterpret_cast<float4*>(&Bs[kk][tx * 8 + 4]);
            #pragma unroll
            for (int i = 0; i < 8; i++)
                #pragma unroll
                for (int j = 0; j < 8; j++)
                    acc[i][j] = fmaf(a[i], b[j], acc[i][j]);
        }
    }

    // ---- epilogue: bias (+ReLU) ----
    const int col0 = bn * BN + tx * 8;
    #pragma unroll
    for (int j = 0; j < 8; j++) {
        const float bb = bias[col0 + j];
        #pragma unroll
        for (int i = 0; i < 8; i++) {
            float v = acc[i][j] + bb;
            if (RELU) v = fmaxf(v, 0.f);
            acc[i][j] = v;
        }
    }

    if (L2NORM) {
        #pragma unroll
        for (int i = 0; i < 8; i++) {
            float s = 0.f;
            #pragma unroll
            for (int j = 0; j < 8; j++) s = fmaf(acc[i][j], acc[i][j], s);
            red[ty * 8 + i][tx] = s;
        }
        __syncthreads();
        if (tid < BM) {
            float s = 0.f;
            #pragma unroll
            for (int t = 0; t < 16; t++) s += red[tid][t];
            scl[tid] = 1.f / fmaxf(sqrtf(s), 1e-12f);
        }
        __syncthreads();
        #pragma unroll
        for (int i = 0; i < 8; i++) {
            const float s = scl[ty * 8 + i];
            #pragma unroll
            for (int j = 0; j < 8; j++) acc[i][j] *= s;
        }
    }

    #pragma unroll
    for (int i = 0; i < 8; i++) {
        const int row = bm * BM + ty * 8 + i;
        if (row < M) {
            float4* dst = reinterpret_cast<float4*>(C + (size_t)row * N + col0);
            dst[0] = *reinterpret_cast<float4*>(&acc[i][0]);
            dst[1] = *reinterpret_cast<float4*>(&acc[i][4]);
        }
    }
}

// ---------------- history gather + mean pool + fuse with gcn_user ----------
__global__ __launch_bounds__(128)
void gather_kernel(const float* __restrict__ gcn_user,
                   const int* __restrict__ hist,
                   const float* __restrict__ item_emb,
                   float* __restrict__ user_feat)
{
    const int u = blockIdx.x;
    const int t = threadIdx.x;  // 0..127 = embedding dim
    __shared__ int sidx[HIST];
    if (t < HIST) sidx[t] = hist[u * HIST + t];
    __syncthreads();

    float s = 0.f;
    #pragma unroll
    for (int j = 0; j < HIST; j++)
        s += item_emb[(size_t)sidx[j] * TOWER_DIM + t];

    user_feat[(size_t)u * (GCN_DIM + TOWER_DIM) + t]           = gcn_user[(size_t)u * GCN_DIM + t];
    user_feat[(size_t)u * (GCN_DIM + TOWER_DIM) + GCN_DIM + t] = s * (1.0f / HIST);
}

// ---------------- launch -----------------------------------------------------
extern "C" void kernel_launch(void* const* d_in, const int* in_sizes, int n_in,
                              void* d_out, int out_size)
{
    const float* item_text = (const float*)d_in[0];
    const float* gcn_item  = (const float*)d_in[1];
    const float* gcn_user  = (const float*)d_in[2];
    const int*   hist      = (const int*)  d_in[3];
    const float* W1i = (const float*)d_in[4];
    const float* b1i = (const float*)d_in[5];
    const float* W2i = (const float*)d_in[6];
    const float* b2i = (const float*)d_in[7];
    const float* W1u = (const float*)d_in[8];
    const float* b1u = (const float*)d_in[9];
    const float* W2u = (const float*)d_in[10];
    const float* b2u = (const float*)d_in[11];
    float* out = (float*)d_out;

    float *pH, *pItem, *pUF, *pHu;
    cudaGetSymbolAddress((void**)&pH,    g_H);
    cudaGetSymbolAddress((void**)&pItem, g_item_emb);
    cudaGetSymbolAddress((void**)&pUF,   g_user_feat);
    cudaGetSymbolAddress((void**)&pHu,   g_Hu);

    const dim3 blk(256);

    // Item tower layer 1: H = relu(concat(text, gcn_item) @ W1i + b1i)
    sgemm<true, false><<<dim3(HIDDEN_DIM / 128, CDIV(N_ITEMS, 128)), blk>>>(
        item_text, gcn_item, TEXT_DIM,
        N_ITEMS, HIDDEN_DIM, TEXT_DIM + GCN_DIM, W1i, b1i, pH);

    // Item tower layer 2: item_emb = l2norm(H @ W2i + b2i)
    sgemm<false, true><<<dim3(1, CDIV(N_ITEMS, 128)), blk>>>(
        pH, nullptr, HIDDEN_DIM,
        N_ITEMS, TOWER_DIM, HIDDEN_DIM, W2i, b2i, pItem);

    // History gather + mean pool, fused with gcn_user into user_feat
    gather_kernel<<<N_USERS, 128>>>(gcn_user, hist, pItem, pUF);

    // User tower layer 1: Hu = relu(user_feat @ W1u + b1u)
    sgemm<true, false><<<dim3(HIDDEN_DIM / 128, CDIV(N_USERS, 128)), blk>>>(
        pUF, nullptr, GCN_DIM + TOWER_DIM,
        N_USERS, HIDDEN_DIM, GCN_DIM + TOWER_DIM, W1u, b1u, pHu);

    // User tower layer 2: out = l2norm(Hu @ W2u + b2u)
    sgemm<false, true><<<dim3(1, CDIV(N_USERS, 128)), blk>>>(
        pHu, nullptr, HIDDEN_DIM,
        N_USERS, TOWER_DIM, HIDDEN_DIM, W2u, b2u, out);
}

// round 5
// speedup vs baseline: 1.9689x; 1.9689x over previous
#include <cuda_runtime.h>
#include <cstdint>
#include <cstddef>

#define N_ITEMS   100000
#define N_USERS   16384
#define HIST      50
#define TEXT_DIM  256
#define GCN_DIM   128
#define HIDDEN_DIM 512
#define TOWER_DIM 128

#define CDIV(a,b) (((a)+(b)-1)/(b))

// ---------------- scratch (device globals; no allocation allowed) ----------
__device__ float g_H[(size_t)N_ITEMS * HIDDEN_DIM];        // item hidden
__device__ float g_item_emb[(size_t)N_ITEMS * TOWER_DIM];  // item tower out
__device__ float g_user_feat[(size_t)N_USERS * (GCN_DIM + TOWER_DIM)];
__device__ float g_Hu[(size_t)N_USERS * HIDDEN_DIM];

__device__ __forceinline__ unsigned f2tf32(float x) {
    unsigned r;
    asm("cvt.rna.tf32.f32 %0, %1;" : "=r"(r) : "f"(x));
    return r;
}

__device__ __forceinline__ void mma_tf32(float* d, const unsigned* a, const unsigned* b) {
    asm volatile(
        "mma.sync.aligned.m16n8k8.row.col.f32.tf32.tf32.f32 "
        "{%0,%1,%2,%3}, {%4,%5,%6,%7}, {%8,%9}, {%0,%1,%2,%3};\n"
        : "+f"(d[0]), "+f"(d[1]), "+f"(d[2]), "+f"(d[3])
        : "r"(a[0]), "r"(a[1]), "r"(a[2]), "r"(a[3]), "r"(b[0]), "r"(b[1]));
}

// ---------------- TF32 tensor-core GEMM: C = op(A @ B + bias) --------------
// A logical [M,K]; col c < split from A0 (lda=split) else A1 (lda=K-split).
// B [K,N] row-major.  BM=BN=128, BK=32, 256 threads (8 warps, 64x32 warp tile,
// 4x4 grid of m16n8k8 fragments per warp).  L2NORM requires N==128 (gridDim.x==1).
template<bool RELU, bool L2NORM>
__global__ __launch_bounds__(256, 2)
void mma_gemm(const float* __restrict__ A0, const float* __restrict__ A1, int split,
              int M, int N, int K,
              const float* __restrict__ B, const float* __restrict__ bias,
              float* __restrict__ C)
{
    constexpr int BM = 128, BN = 128, BK = 32;
    constexpr int LDA = BM + 8;   // pad 8 -> fragment LDS hits all 32 banks
    constexpr int LDB = BN + 8;
    __shared__ unsigned As[BK][LDA];   // tf32 bits, [k][m]
    __shared__ unsigned Bs[BK][LDB];   // tf32 bits, [k][n]
    __shared__ float red[BM][17];
    __shared__ float scl[BM];

    const int tid  = threadIdx.x;
    const int warp = tid >> 5, lane = tid & 31;
    const int wy = warp >> 2, wx = warp & 3;     // warp tile: rows wy*64, cols wx*32
    const int g  = lane >> 2, t4 = lane & 3;     // fragment lane decomposition
    const int bm = blockIdx.y, bn = blockIdx.x;
    const int lda1 = K - split;

    float acc[4][4][4];   // [mi][ni][frag]
    #pragma unroll
    for (int i = 0; i < 4; i++)
        #pragma unroll
        for (int j = 0; j < 4; j++)
            #pragma unroll
            for (int r = 0; r < 4; r++) acc[i][j][r] = 0.f;

    for (int k0 = 0; k0 < K; k0 += BK) {
        // ---- stage global loads in registers ----
        float4 avv[4], bvv[4];
        #pragma unroll
        for (int c = 0; c < 4; c++) {
            const int idx = tid + c * 256;
            const int m = idx >> 3, kc = (idx & 7) * 4;
            const int grow = bm * BM + m;
            float4 av = make_float4(0.f, 0.f, 0.f, 0.f);
            if (grow < M) {
                const int ac = k0 + kc;
                const float* src = (ac < split)
                    ? (A0 + (size_t)grow * split + ac)
                    : (A1 + (size_t)grow * lda1 + (ac - split));
                av = *reinterpret_cast<const float4*>(src);
            }
            avv[c] = av;
            const int kb = idx >> 5, nb = (idx & 31) * 4;
            bvv[c] = *reinterpret_cast<const float4*>(
                B + (size_t)(k0 + kb) * N + (size_t)bn * BN + nb);
        }

        __syncthreads();
        #pragma unroll
        for (int c = 0; c < 4; c++) {
            const int idx = tid + c * 256;
            const int m = idx >> 3, kc = (idx & 7) * 4;
            As[kc + 0][m] = f2tf32(avv[c].x);
            As[kc + 1][m] = f2tf32(avv[c].y);
            As[kc + 2][m] = f2tf32(avv[c].z);
            As[kc + 3][m] = f2tf32(avv[c].w);
            const int kb = idx >> 5, nb = (idx & 31) * 4;
            uint4 bt;
            bt.x = f2tf32(bvv[c].x); bt.y = f2tf32(bvv[c].y);
            bt.z = f2tf32(bvv[c].z); bt.w = f2tf32(bvv[c].w);
            *reinterpret_cast<uint4*>(&Bs[kb][nb]) = bt;
        }
        __syncthreads();

        // ---- 4 k-steps of 8 ----
        #pragma unroll
        for (int ks = 0; ks < 4; ks++) {
            const int kb = ks * 8;
            unsigned a[4][4], b[4][2];
            #pragma unroll
            for (int mi = 0; mi < 4; mi++) {
                const int rb = wy * 64 + mi * 16;
                a[mi][0] = As[kb + t4][rb + g];
                a[mi][1] = As[kb + t4][rb + 8 + g];
                a[mi][2] = As[kb + 4 + t4][rb + g];
                a[mi][3] = As[kb + 4 + t4][rb + 8 + g];
            }
            #pragma unroll
            for (int ni = 0; ni < 4; ni++) {
                const int nb = wx * 32 + ni * 8;
                b[ni][0] = Bs[kb + t4][nb + g];
                b[ni][1] = Bs[kb + 4 + t4][nb + g];
            }
            #pragma unroll
            for (int mi = 0; mi < 4; mi++)
                #pragma unroll
                for (int ni = 0; ni < 4; ni++)
                    mma_tf32(acc[mi][ni], a[mi], b[ni]);
        }
    }

    // ---- epilogue: bias (+ReLU) ----
    #pragma unroll
    for (int ni = 0; ni < 4; ni++) {
        const int colw = wx * 32 + ni * 8 + t4 * 2;
        const float b0 = bias[bn * BN + colw];
        const float b1 = bias[bn * BN + colw + 1];
        #pragma unroll
        for (int mi = 0; mi < 4; mi++) {
            float v0 = acc[mi][ni][0] + b0;
            float v1 = acc[mi][ni][1] + b1;
            float v2 = acc[mi][ni][2] + b0;
            float v3 = acc[mi][ni][3] + b1;
            if (RELU) {
                v0 = fmaxf(v0, 0.f); v1 = fmaxf(v1, 0.f);
                v2 = fmaxf(v2, 0.f); v3 = fmaxf(v3, 0.f);
            }
            acc[mi][ni][0] = v0; acc[mi][ni][1] = v1;
            acc[mi][ni][2] = v2; acc[mi][ni][3] = v3;
        }
    }

    if (L2NORM) {
        const int slot = wx * 4 + t4;
        #pragma unroll
        for (int mi = 0; mi < 4; mi++) {
            const int rb = wy * 64 + mi * 16;
            float s0 = 0.f, s1 = 0.f;
            #pragma unroll
            for (int ni = 0; ni < 4; ni++) {
                s0 = fmaf(acc[mi][ni][0], acc[mi][ni][0], s0);
                s0 = fmaf(acc[mi][ni][1], acc[mi][ni][1], s0);
                s1 = fmaf(acc[mi][ni][2], acc[mi][ni][2], s1);
                s1 = fmaf(acc[mi][ni][3], acc[mi][ni][3], s1);
            }
            red[rb + g][slot]     = s0;
            red[rb + 8 + g][slot] = s1;
        }
        __syncthreads();
        if (tid < BM) {
            float s = 0.f;
            #pragma unroll
            for (int t = 0; t < 16; t++) s += red[tid][t];
            scl[tid] = 1.f / fmaxf(sqrtf(s), 1e-12f);
        }
        __syncthreads();
        #pragma unroll
        for (int mi = 0; mi < 4; mi++) {
            const int rb = wy * 64 + mi * 16;
            const float s0 = scl[rb + g];
            const float s1 = scl[rb + 8 + g];
            #pragma unroll
            for (int ni = 0; ni < 4; ni++) {
                acc[mi][ni][0] *= s0; acc[mi][ni][1] *= s0;
                acc[mi][ni][2] *= s1; acc[mi][ni][3] *= s1;
            }
        }
    }

    // ---- store (float2 per fragment half-row) ----
    #pragma unroll
    for (int mi = 0; mi < 4; mi++) {
        const int row0 = bm * BM + wy * 64 + mi * 16 + g;
        const int row1 = row0 + 8;
        #pragma unroll
        for (int ni = 0; ni < 4; ni++) {
            const int col = bn * BN + wx * 32 + ni * 8 + t4 * 2;
            if (row0 < M) {
                float2 v = make_float2(acc[mi][ni][0], acc[mi][ni][1]);
                *reinterpret_cast<float2*>(C + (size_t)row0 * N + col) = v;
            }
            if (row1 < M) {
                float2 v = make_float2(acc[mi][ni][2], acc[mi][ni][3]);
                *reinterpret_cast<float2*>(C + (size_t)row1 * N + col) = v;
            }
        }
    }
}

// ---------------- history gather + mean pool + fuse with gcn_user ----------
__global__ __launch_bounds__(128)
void gather_kernel(const float* __restrict__ gcn_user,
                   const int* __restrict__ hist,
                   const float* __restrict__ item_emb,
                   float* __restrict__ user_feat)
{
    const int u = blockIdx.x;
    const int t = threadIdx.x;  // 0..127 = embedding dim
    __shared__ int sidx[HIST];
    if (t < HIST) sidx[t] = hist[u * HIST + t];
    __syncthreads();

    float s = 0.f;
    #pragma unroll
    for (int j = 0; j < HIST; j++)
        s += item_emb[(size_t)sidx[j] * TOWER_DIM + t];

    user_feat[(size_t)u * (GCN_DIM + TOWER_DIM) + t]           = gcn_user[(size_t)u * GCN_DIM + t];
    user_feat[(size_t)u * (GCN_DIM + TOWER_DIM) + GCN_DIM + t] = s * (1.0f / HIST);
}

// ---------------- launch -----------------------------------------------------
extern "C" void kernel_launch(void* const* d_in, const int* in_sizes, int n_in,
                              void* d_out, int out_size)
{
    const float* item_text = (const float*)d_in[0];
    const float* gcn_item  = (const float*)d_in[1];
    const float* gcn_user  = (const float*)d_in[2];
    const int*   hist      = (const int*)  d_in[3];
    const float* W1i = (const float*)d_in[4];
    const float* b1i = (const float*)d_in[5];
    const float* W2i = (const float*)d_in[6];
    const float* b2i = (const float*)d_in[7];
    const float* W1u = (const float*)d_in[8];
    const float* b1u = (const float*)d_in[9];
    const float* W2u = (const float*)d_in[10];
    const float* b2u = (const float*)d_in[11];
    float* out = (float*)d_out;

    float *pH, *pItem, *pUF, *pHu;
    cudaGetSymbolAddress((void**)&pH,    g_H);
    cudaGetSymbolAddress((void**)&pItem, g_item_emb);
    cudaGetSymbolAddress((void**)&pUF,   g_user_feat);
    cudaGetSymbolAddress((void**)&pHu,   g_Hu);

    const dim3 blk(256);

    // Item tower layer 1: H = relu(concat(text, gcn_item) @ W1i + b1i)
    mma_gemm<true, false><<<dim3(HIDDEN_DIM / 128, CDIV(N_ITEMS, 128)), blk>>>(
        item_text, gcn_item, TEXT_DIM,
        N_ITEMS, HIDDEN_DIM, TEXT_DIM + GCN_DIM, W1i, b1i, pH);

    // Item tower layer 2: item_emb = l2norm(H @ W2i + b2i)
    mma_gemm<false, true><<<dim3(1, CDIV(N_ITEMS, 128)), blk>>>(
        pH, nullptr, HIDDEN_DIM,
        N_ITEMS, TOWER_DIM, HIDDEN_DIM, W2i, b2i, pItem);

    // History gather + mean pool fused with gcn_user
    gather_kernel<<<N_USERS, 128>>>(gcn_user, hist, pItem, pUF);

    // User tower layer 1: Hu = relu(user_feat @ W1u + b1u)
    mma_gemm<true, false><<<dim3(HIDDEN_DIM / 128, CDIV(N_USERS, 128)), blk>>>(
        pUF, nullptr, GCN_DIM + TOWER_DIM,
        N_USERS, HIDDEN_DIM, GCN_DIM + TOWER_DIM, W1u, b1u, pHu);

    // User tower layer 2: out = l2norm(Hu @ W2u + b2u)
    mma_gemm<false, true><<<dim3(1, CDIV(N_USERS, 128)), blk>>>(
        pHu, nullptr, HIDDEN_DIM,
        N_USERS, TOWER_DIM, HIDDEN_DIM, W2u, b2u, out);
}

// round 6
// speedup vs baseline: 3.1101x; 1.5796x over previous
#include <cuda_runtime.h>
#include <cstdint>
#include <cstddef>

#define N_ITEMS   100000
#define N_USERS   16384
#define HIST      50
#define TEXT_DIM  256
#define GCN_DIM   128
#define HIDDEN_DIM 512
#define TOWER_DIM 128

#define CDIV(a,b) (((a)+(b)-1)/(b))

// ---------------- scratch (device globals; no allocation allowed) ----------
__device__ float g_H[(size_t)N_ITEMS * HIDDEN_DIM];        // item hidden
__device__ float g_item_emb[(size_t)N_ITEMS * TOWER_DIM];  // item tower out
__device__ float g_user_feat[(size_t)N_USERS * (GCN_DIM + TOWER_DIM)];
__device__ float g_Hu[(size_t)N_USERS * HIDDEN_DIM];

__device__ __forceinline__ unsigned f2tf32(float x) {
    unsigned r;
    asm("cvt.rna.tf32.f32 %0, %1;" : "=r"(r) : "f"(x));
    return r;
}

__device__ __forceinline__ void mma_tf32(float* d, const unsigned* a, const unsigned* b) {
    asm volatile(
        "mma.sync.aligned.m16n8k8.row.col.f32.tf32.tf32.f32 "
        "{%0,%1,%2,%3}, {%4,%5,%6,%7}, {%8,%9}, {%0,%1,%2,%3};\n"
        : "+f"(d[0]), "+f"(d[1]), "+f"(d[2]), "+f"(d[3])
        : "r"(a[0]), "r"(a[1]), "r"(a[2]), "r"(a[3]), "r"(b[0]), "r"(b[1]));
}

__device__ __forceinline__ void cp16(uint32_t dst, const void* src, int szbytes) {
    asm volatile("cp.async.ca.shared.global [%0], [%1], 16, %2;"
                 :: "r"(dst), "l"(src), "r"(szbytes));
}

// ---------------- TF32 tensor-core GEMM, cp.async double-buffered ----------
// A logical [M,K]; col c < split from A0 (lda=split) else A1 (lda=K-split).
// B [K,N] row-major.  BM=BN=128, BK=16, 256 threads (8 warps, 64x32 warp
// tile, 4x4 m16n8k8 fragments).  fp32 kept in smem; cvt.rna.tf32 at fragment
// load (same numerics as R5).  L2NORM requires N==128 (gridDim.x==1).
template<bool RELU, bool L2NORM>
__global__ __launch_bounds__(256, 2)
void mma_gemm(const float* __restrict__ A0, const float* __restrict__ A1, int split,
              int M, int N, int K,
              const float* __restrict__ B, const float* __restrict__ bias,
              float* __restrict__ C)
{
    constexpr int BM = 128, BN = 128, BK = 16;
    constexpr int LDA = BK + 4;      // 20 floats: (20g+t4)%32 hits all 32 banks
    constexpr int LDB = BN + 8;      // 136 floats: (136k+g)%32 conflict-free
    constexpr int A_BUF = BM * LDA;  // 2560 floats / buffer
    constexpr int B_BUF = BK * LDB;  // 2176 floats / buffer
    __shared__ __align__(16) float smem[2 * A_BUF + 2 * B_BUF];  // 37,888 B

    float* As = smem;                       // [2][BM][LDA], fp32
    float* Bs = smem + 2 * A_BUF;           // [2][BK][LDB], fp32
    // epilogue scratch aliases buffer 0 of As (used only after the main loop)
    float (*red)[17] = reinterpret_cast<float(*)[17]>(smem);
    float* scl = smem + BM * 17;

    const int tid  = threadIdx.x;
    const int warp = tid >> 5, lane = tid & 31;
    const int wy = warp >> 2, wx = warp & 3;     // warp tile: rows wy*64, cols wx*32
    const int g  = lane >> 2, t4 = lane & 3;     // fragment lane decomposition
    const int bm = blockIdx.y, bn = blockIdx.x;
    const int lda1 = K - split;

    const uint32_t a_base = (uint32_t)__cvta_generic_to_shared(As);
    const uint32_t b_base = (uint32_t)__cvta_generic_to_shared(Bs);

    float acc[4][4][4];
    #pragma unroll
    for (int i = 0; i < 4; i++)
        #pragma unroll
        for (int j = 0; j < 4; j++)
            #pragma unroll
            for (int r = 0; r < 4; r++) acc[i][j][r] = 0.f;

    // ---- cp.async tile issue: A 512x16B chunks + B 512x16B chunks ----
    auto issue = [&](int k0, int buf) {
        #pragma unroll
        for (int c = 0; c < 2; c++) {
            const int id = tid + c * 256;        // 0..511
            const int m  = id >> 2;              // 0..127
            const int f  = (id & 3) * 4;         // k offset 0,4,8,12
            const int grow = bm * BM + m;
            const int ac = k0 + f;
            const float* src = A0;
            int sz = 0;
            if (grow < M) {
                src = (ac < split) ? (A0 + (size_t)grow * split + ac)
                                   : (A1 + (size_t)grow * lda1 + (ac - split));
                sz = 16;
            }
            cp16(a_base + (uint32_t)(buf * A_BUF + m * LDA + f) * 4, src, sz);
        }
        #pragma unroll
        for (int c = 0; c < 2; c++) {
            const int id = tid + c * 256;
            const int kb = id >> 5;              // 0..15
            const int nb = (id & 31) * 4;
            const float* src = B + (size_t)(k0 + kb) * N + (size_t)bn * BN + nb;
            cp16(b_base + (uint32_t)(buf * B_BUF + kb * LDB + nb) * 4, src, 16);
        }
        asm volatile("cp.async.commit_group;");
    };

    const int NT = K / BK;
    issue(0, 0);

    for (int it = 0; it < NT; it++) {
        const int buf = it & 1;
        if (it + 1 < NT) {
            issue((it + 1) * BK, buf ^ 1);
            asm volatile("cp.async.wait_group 1;");
        } else {
            asm volatile("cp.async.wait_group 0;");
        }
        __syncthreads();

        const float* Ab = As + buf * A_BUF;
        const float* Bb = Bs + buf * B_BUF;

        #pragma unroll
        for (int ks = 0; ks < 2; ks++) {
            const int kb = ks * 8;
            unsigned a[4][4], b[4][2];
            #pragma unroll
            for (int mi = 0; mi < 4; mi++) {
                const int rb = wy * 64 + mi * 16;
                a[mi][0] = f2tf32(Ab[(rb + g)     * LDA + kb + t4]);
                a[mi][1] = f2tf32(Ab[(rb + 8 + g) * LDA + kb + t4]);
                a[mi][2] = f2tf32(Ab[(rb + g)     * LDA + kb + 4 + t4]);
                a[mi][3] = f2tf32(Ab[(rb + 8 + g) * LDA + kb + 4 + t4]);
            }
            #pragma unroll
            for (int ni = 0; ni < 4; ni++) {
                const int nbc = wx * 32 + ni * 8;
                b[ni][0] = f2tf32(Bb[(kb + t4)     * LDB + nbc + g]);
                b[ni][1] = f2tf32(Bb[(kb + 4 + t4) * LDB + nbc + g]);
            }
            #pragma unroll
            for (int mi = 0; mi < 4; mi++)
                #pragma unroll
                for (int ni = 0; ni < 4; ni++)
                    mma_tf32(acc[mi][ni], a[mi], b[ni]);
        }
        __syncthreads();
    }

    // ---- epilogue: bias (+ReLU) ----
    #pragma unroll
    for (int ni = 0; ni < 4; ni++) {
        const int colw = wx * 32 + ni * 8 + t4 * 2;
        const float b0 = bias[bn * BN + colw];
        const float b1 = bias[bn * BN + colw + 1];
        #pragma unroll
        for (int mi = 0; mi < 4; mi++) {
            float v0 = acc[mi][ni][0] + b0;
            float v1 = acc[mi][ni][1] + b1;
            float v2 = acc[mi][ni][2] + b0;
            float v3 = acc[mi][ni][3] + b1;
            if (RELU) {
                v0 = fmaxf(v0, 0.f); v1 = fmaxf(v1, 0.f);
                v2 = fmaxf(v2, 0.f); v3 = fmaxf(v3, 0.f);
            }
            acc[mi][ni][0] = v0; acc[mi][ni][1] = v1;
            acc[mi][ni][2] = v2; acc[mi][ni][3] = v3;
        }
    }

    if (L2NORM) {
        const int slot = wx * 4 + t4;
        #pragma unroll
        for (int mi = 0; mi < 4; mi++) {
            const int rb = wy * 64 + mi * 16;
            float s0 = 0.f, s1 = 0.f;
            #pragma unroll
            for (int ni = 0; ni < 4; ni++) {
                s0 = fmaf(acc[mi][ni][0], acc[mi][ni][0], s0);
                s0 = fmaf(acc[mi][ni][1], acc[mi][ni][1], s0);
                s1 = fmaf(acc[mi][ni][2], acc[mi][ni][2], s1);
                s1 = fmaf(acc[mi][ni][3], acc[mi][ni][3], s1);
            }
            red[rb + g][slot]     = s0;
            red[rb + 8 + g][slot] = s1;
        }
        __syncthreads();
        if (tid < BM) {
            float s = 0.f;
            #pragma unroll
            for (int t = 0; t < 16; t++) s += red[tid][t];
            scl[tid] = 1.f / fmaxf(sqrtf(s), 1e-12f);
        }
        __syncthreads();
        #pragma unroll
        for (int mi = 0; mi < 4; mi++) {
            const int rb = wy * 64 + mi * 16;
            const float s0 = scl[rb + g];
            const float s1 = scl[rb + 8 + g];
            #pragma unroll
            for (int ni = 0; ni < 4; ni++) {
                acc[mi][ni][0] *= s0; acc[mi][ni][1] *= s0;
                acc[mi][ni][2] *= s1; acc[mi][ni][3] *= s1;
            }
        }
    }

    // ---- store (float2 per fragment half-row) ----
    #pragma unroll
    for (int mi = 0; mi < 4; mi++) {
        const int row0 = bm * BM + wy * 64 + mi * 16 + g;
        const int row1 = row0 + 8;
        #pragma unroll
        for (int ni = 0; ni < 4; ni++) {
            const int col = bn * BN + wx * 32 + ni * 8 + t4 * 2;
            if (row0 < M) {
                float2 v = make_float2(acc[mi][ni][0], acc[mi][ni][1]);
                *reinterpret_cast<float2*>(C + (size_t)row0 * N + col) = v;
            }
            if (row1 < M) {
                float2 v = make_float2(acc[mi][ni][2], acc[mi][ni][3]);
                *reinterpret_cast<float2*>(C + (size_t)row1 * N + col) = v;
            }
        }
    }
}

// ---------------- history gather + mean pool + fuse with gcn_user ----------
__global__ __launch_bounds__(128)
void gather_kernel(const float* __restrict__ gcn_user,
                   const int* __restrict__ hist,
                   const float* __restrict__ item_emb,
                   float* __restrict__ user_feat)
{
    const int u = blockIdx.x;
    const int t = threadIdx.x;  // 0..127 = embedding dim
    __shared__ int sidx[HIST];
    if (t < HIST) sidx[t] = hist[u * HIST + t];
    __syncthreads();

    float s = 0.f;
    #pragma unroll
    for (int j = 0; j < HIST; j++)
        s += item_emb[(size_t)sidx[j] * TOWER_DIM + t];

    user_feat[(size_t)u * (GCN_DIM + TOWER_DIM) + t]           = gcn_user[(size_t)u * GCN_DIM + t];
    user_feat[(size_t)u * (GCN_DIM + TOWER_DIM) + GCN_DIM + t] = s * (1.0f / HIST);
}

// ---------------- launch -----------------------------------------------------
extern "C" void kernel_launch(void* const* d_in, const int* in_sizes, int n_in,
                              void* d_out, int out_size)
{
    const float* item_text = (const float*)d_in[0];
    const float* gcn_item  = (const float*)d_in[1];
    const float* gcn_user  = (const float*)d_in[2];
    const int*   hist      = (const int*)  d_in[3];
    const float* W1i = (const float*)d_in[4];
    const float* b1i = (const float*)d_in[5];
    const float* W2i = (const float*)d_in[6];
    const float* b2i = (const float*)d_in[7];
    const float* W1u = (const float*)d_in[8];
    const float* b1u = (const float*)d_in[9];
    const float* W2u = (const float*)d_in[10];
    const float* b2u = (const float*)d_in[11];
    float* out = (float*)d_out;

    float *pH, *pItem, *pUF, *pHu;
    cudaGetSymbolAddress((void**)&pH,    g_H);
    cudaGetSymbolAddress((void**)&pItem, g_item_emb);
    cudaGetSymbolAddress((void**)&pUF,   g_user_feat);
    cudaGetSymbolAddress((void**)&pHu,   g_Hu);

    const dim3 blk(256);

    // Item tower layer 1: H = relu(concat(text, gcn_item) @ W1i + b1i)
    mma_gemm<true, false><<<dim3(HIDDEN_DIM / 128, CDIV(N_ITEMS, 128)), blk>>>(
        item_text, gcn_item, TEXT_DIM,
        N_ITEMS, HIDDEN_DIM, TEXT_DIM + GCN_DIM, W1i, b1i, pH);

    // Item tower layer 2: item_emb = l2norm(H @ W2i + b2i)
    mma_gemm<false, true><<<dim3(1, CDIV(N_ITEMS, 128)), blk>>>(
        pH, nullptr, HIDDEN_DIM,
        N_ITEMS, TOWER_DIM, HIDDEN_DIM, W2i, b2i, pItem);

    // History gather + mean pool fused with gcn_user
    gather_kernel<<<N_USERS, 128>>>(gcn_user, hist, pItem, pUF);

    // User tower layer 1: Hu = relu(user_feat @ W1u + b1u)
    mma_gemm<true, false><<<dim3(HIDDEN_DIM / 128, CDIV(N_USERS, 128)), blk>>>(
        pUF, nullptr, GCN_DIM + TOWER_DIM,
        N_USERS, HIDDEN_DIM, GCN_DIM + TOWER_DIM, W1u, b1u, pHu);

    // User tower layer 2: out = l2norm(Hu @ W2u + b2u)
    mma_gemm<false, true><<<dim3(1, CDIV(N_USERS, 128)), blk>>>(
        pHu, nullptr, HIDDEN_DIM,
        N_USERS, TOWER_DIM, HIDDEN_DIM, W2u, b2u, out);
}